// round 2
// baseline (speedup 1.0000x reference)
#include <cuda_runtime.h>
#include <cstdint>

#define LEN 4096
#define HH 256
#define NHEADS 4
#define PPAD 512
#define NP (LEN + 2*PPAD + 1)   // 5121

// Prebuilt normalized weights: [h][i*32+m][c]
__device__ float g_W[HH * 192 * NHEADS];

__device__ __forceinline__ unsigned long long pk2(float a, float b) {
    unsigned long long r;
    asm("mov.b64 %0, {%1, %2};" : "=l"(r) : "r"(__float_as_uint(a)), "r"(__float_as_uint(b)));
    return r;
}
__device__ __forceinline__ void upk2(unsigned long long v, float& a, float& b) {
    unsigned int lo, hi;
    asm("mov.b64 {%0, %1}, %2;" : "=r"(lo), "=r"(hi) : "l"(v));
    a = __uint_as_float(lo); b = __uint_as_float(hi);
}
__device__ __forceinline__ unsigned long long fma2(unsigned long long a, unsigned long long b, unsigned long long c) {
    unsigned long long d;
    asm("fma.rn.f32x2 %0, %1, %2, %3;" : "=l"(d) : "l"(a), "l"(b), "l"(c));
    return d;
}
__device__ __forceinline__ unsigned long long mul2(unsigned long long a, unsigned long long b) {
    unsigned long long d;
    asm("mul.rn.f32x2 %0, %1, %2;" : "=l"(d) : "l"(a), "l"(b));
    return d;
}

// Build effective compressed kernel weights.
// k_raw[j] for scale i = kernels[i,c,h,m] * 2^(5-i), repeated rep_i times.
// norm^2[c,h] = sum_i rep_i * 4^(5-i) * sum_m kernels[i,c,h,m]^2
__global__ void build_weights_kernel(const float* __restrict__ kers) {
    int h = blockIdx.x;
    int c = threadIdx.x >> 5;
    int lane = threadIdx.x & 31;
    const float normw[6] = {1024.f, 256.f, 128.f, 64.f, 32.f, 16.f};
    const float sc[6]    = {32.f, 16.f, 8.f, 4.f, 2.f, 1.f};

    float vals[6];
    float ss = 0.f;
#pragma unroll
    for (int i = 0; i < 6; i++) {
        float v = kers[((i * 4 + c) * HH + h) * 32 + lane];
        vals[i] = v * sc[i];
        ss += v * v * normw[i];
    }
#pragma unroll
    for (int o = 16; o; o >>= 1) ss += __shfl_xor_sync(0xffffffffu, ss, o);
    float inv = 1.0f / sqrtf(ss);
#pragma unroll
    for (int i = 0; i < 6; i++) {
        g_W[(h * 192 + i * 32 + lane) * 4 + c] = vals[i] * inv;
    }
}

// One CTA per (b, h) row. 256 threads.
// out[b, h*4+c, l] = sum_{i,m} W[c,h,i,m] * (P[q] - P[q - r_i]),  q = l+513-O_i-m*r_i
//                  + x[l] * D[c,h]
__global__ __launch_bounds__(256) void conv_kernel(
    const float* __restrict__ x,
    const float* __restrict__ D,
    float* __restrict__ out)
{
    __shared__ float Xsh[LEN];
    __shared__ float Psh[NP];
    __shared__ unsigned long long Wsh[192 * 4];  // duplicated (w,w) pairs
    __shared__ float wsum[8];

    const int t  = threadIdx.x;
    const int h  = blockIdx.x & 255;
    const int bb = blockIdx.x >> 8;
    const float* xr = x + (size_t)(bb * HH + h) * LEN;

    // Stage x coalesced into shared
#pragma unroll
    for (int it = 0; it < 16; it++) Xsh[t + 256 * it] = xr[t + 256 * it];

    // Load + duplicate weights
#pragma unroll
    for (int it = 0; it < 3; it++) {
        int idx = t + 256 * it;
        float w = g_W[h * 768 + idx];
        Wsh[idx] = pk2(w, w);
    }

    // Zero left pad of P
    Psh[t] = 0.f;
    Psh[t + 256] = 0.f;
    __syncthreads();

    // ---- block-wide inclusive prefix sum of x into Psh[PPAD + 1 + j] ----
    float r[16];
    float run = 0.f;
#pragma unroll
    for (int u = 0; u < 16; u++) { run += Xsh[16 * t + u]; r[u] = run; }
    float s = run;
    float incl = s;
#pragma unroll
    for (int o = 1; o < 32; o <<= 1) {
        float v = __shfl_up_sync(0xffffffffu, incl, o);
        if ((t & 31) >= o) incl += v;
    }
    if ((t & 31) == 31) wsum[t >> 5] = incl;
    __syncthreads();
    float woff = 0.f, Tot = 0.f;
#pragma unroll
    for (int wdx = 0; wdx < 8; wdx++) {
        float v = wsum[wdx];
        Tot += v;
        if (wdx < (t >> 5)) woff += v;
    }
    float e = woff + (incl - s);
#pragma unroll
    for (int u = 0; u < 16; u++) Psh[PPAD + 16 * t + u + 1] = e + r[u];
    if (t == 0) Psh[PPAD] = 0.f;
    // Right pad: P[q>=4096] = total
    Psh[PPAD + LEN + 1 + t] = Tot;
    Psh[PPAD + LEN + 1 + t + 256] = Tot;
    __syncthreads();

    // ---- main convolution ----
    typedef unsigned long long u64;
    const u64 NEG1 = pk2(-1.0f, -1.0f);

    u64 acc[4][8];
    // skip: acc = x * D[c,h]
    u64 Dd[4];
#pragma unroll
    for (int c = 0; c < 4; c++) {
        float dv = D[c * HH + h];
        Dd[c] = pk2(dv, dv);
    }
#pragma unroll
    for (int j = 0; j < 8; j++) {
        int l0 = t + 512 * j;                 // lo l; hi = l0 + 256
        u64 x2 = pk2(Xsh[l0], Xsh[l0 + 256]);
#pragma unroll
        for (int c = 0; c < 4; c++) acc[c][j] = mul2(x2, Dd[c]);
    }

    const int O_[6] = {0, 32, 64, 128, 256, 512};
    const int R_[6] = {1, 1, 2, 4, 8, 16};
#pragma unroll
    for (int i = 0; i < 6; i++) {
        const int O = O_[i];
        const int R = R_[i];
        const int base = PPAD + t + 513 - O;  // min index 1, max 5120: in range
        u64 prev[8];
#pragma unroll
        for (int j = 0; j < 8; j++)
            prev[j] = pk2(Psh[base + 512 * j], Psh[base + 512 * j + 256]);
        const u64* wp = &Wsh[(i * 32) * 4];
        int off = base - R;
#pragma unroll 2
        for (int m = 0; m < 32; m++) {
            u64 w0 = wp[4 * m + 0];
            u64 w1 = wp[4 * m + 1];
            u64 w2 = wp[4 * m + 2];
            u64 w3 = wp[4 * m + 3];
#pragma unroll
            for (int j = 0; j < 8; j++) {
                u64 cur = pk2(Psh[off + 512 * j], Psh[off + 512 * j + 256]);
                u64 g = fma2(cur, NEG1, prev[j]);   // prev - cur
                prev[j] = cur;
                acc[0][j] = fma2(g, w0, acc[0][j]);
                acc[1][j] = fma2(g, w1, acc[1][j]);
                acc[2][j] = fma2(g, w2, acc[2][j]);
                acc[3][j] = fma2(g, w3, acc[3][j]);
            }
            off -= R;
        }
    }

    // ---- write out: out[((b*256+h)*4 + c)*4096 + l] ----
    float* outb = out + (size_t)(bb * HH + h) * 4 * LEN;
#pragma unroll
    for (int c = 0; c < 4; c++) {
        float* oc = outb + (size_t)c * LEN;
#pragma unroll
        for (int j = 0; j < 8; j++) {
            float lo, hi;
            upk2(acc[c][j], lo, hi);
            oc[t + 512 * j] = lo;
            oc[t + 512 * j + 256] = hi;
        }
    }
}

extern "C" void kernel_launch(void* const* d_in, const int* in_sizes, int n_in,
                              void* d_out, int out_size)
{
    const float* x    = (const float*)d_in[0];
    const float* kers = (const float*)d_in[1];
    const float* D    = (const float*)d_in[2];
    float* out = (float*)d_out;

    build_weights_kernel<<<HH, 128>>>(kers);
    conv_kernel<<<16 * HH, 256>>>(x, D, out);
}

// round 3
// speedup vs baseline: 1.0021x; 1.0021x over previous
#include <cuda_runtime.h>
#include <cstdint>

#define LEN 4096
#define HH 256
#define NHEADS 4
#define PPAD 512
#define NP (LEN + 2*PPAD + 1)   // 5121

// Prebuilt normalized weights: [h][i*32+m][c]
__device__ float g_W[HH * 192 * NHEADS];

__device__ __forceinline__ unsigned long long pk2(float a, float b) {
    unsigned long long r;
    asm("mov.b64 %0, {%1, %2};" : "=l"(r) : "r"(__float_as_uint(a)), "r"(__float_as_uint(b)));
    return r;
}
__device__ __forceinline__ void upk2(unsigned long long v, float& a, float& b) {
    unsigned int lo, hi;
    asm("mov.b64 {%0, %1}, %2;" : "=r"(lo), "=r"(hi) : "l"(v));
    a = __uint_as_float(lo); b = __uint_as_float(hi);
}
__device__ __forceinline__ unsigned long long fma2(unsigned long long a, unsigned long long b, unsigned long long c) {
    unsigned long long d;
    asm("fma.rn.f32x2 %0, %1, %2, %3;" : "=l"(d) : "l"(a), "l"(b), "l"(c));
    return d;
}
__device__ __forceinline__ unsigned long long mul2(unsigned long long a, unsigned long long b) {
    unsigned long long d;
    asm("mul.rn.f32x2 %0, %1, %2;" : "=l"(d) : "l"(a), "l"(b));
    return d;
}

// Build effective compressed kernel weights.
// k_raw[j] for scale i = kernels[i,c,h,m] * 2^(5-i), repeated rep_i times.
// norm^2[c,h] = sum_i rep_i * 4^(5-i) * sum_m kernels[i,c,h,m]^2
__global__ void build_weights_kernel(const float* __restrict__ kers) {
    int h = blockIdx.x;
    int c = threadIdx.x >> 5;
    int lane = threadIdx.x & 31;
    const float normw[6] = {1024.f, 256.f, 128.f, 64.f, 32.f, 16.f};
    const float sc[6]    = {32.f, 16.f, 8.f, 4.f, 2.f, 1.f};

    float vals[6];
    float ss = 0.f;
#pragma unroll
    for (int i = 0; i < 6; i++) {
        float v = kers[((i * 4 + c) * HH + h) * 32 + lane];
        vals[i] = v * sc[i];
        ss += v * v * normw[i];
    }
#pragma unroll
    for (int o = 16; o; o >>= 1) ss += __shfl_xor_sync(0xffffffffu, ss, o);
    float inv = 1.0f / sqrtf(ss);
#pragma unroll
    for (int i = 0; i < 6; i++) {
        g_W[(h * 192 + i * 32 + lane) * 4 + c] = vals[i] * inv;
    }
}

// One CTA per (b, h) row. 256 threads.
// out[b, h*4+c, l] = sum_{i,m} W[c,h,i,m] * (P[q] - P[q - r_i]),  q = l+513-O_i-m*r_i
//                  + x[l] * D[c,h]
__global__ __launch_bounds__(256) void conv_kernel(
    const float* __restrict__ x,
    const float* __restrict__ D,
    float* __restrict__ out)
{
    __shared__ float Xsh[LEN];
    __shared__ float Psh[NP];
    __shared__ unsigned long long Wsh[192 * 4];  // duplicated (w,w) pairs
    __shared__ float wsum[8];

    const int t  = threadIdx.x;
    const int h  = blockIdx.x & 255;
    const int bb = blockIdx.x >> 8;
    const float* xr = x + (size_t)(bb * HH + h) * LEN;

    // Stage x coalesced into shared
#pragma unroll
    for (int it = 0; it < 16; it++) Xsh[t + 256 * it] = xr[t + 256 * it];

    // Load + duplicate weights
#pragma unroll
    for (int it = 0; it < 3; it++) {
        int idx = t + 256 * it;
        float w = g_W[h * 768 + idx];
        Wsh[idx] = pk2(w, w);
    }

    // Zero left pad of P
    Psh[t] = 0.f;
    Psh[t + 256] = 0.f;
    __syncthreads();

    // ---- block-wide inclusive prefix sum of x into Psh[PPAD + 1 + j] ----
    float r[16];
    float run = 0.f;
#pragma unroll
    for (int u = 0; u < 16; u++) { run += Xsh[16 * t + u]; r[u] = run; }
    float s = run;
    float incl = s;
#pragma unroll
    for (int o = 1; o < 32; o <<= 1) {
        float v = __shfl_up_sync(0xffffffffu, incl, o);
        if ((t & 31) >= o) incl += v;
    }
    if ((t & 31) == 31) wsum[t >> 5] = incl;
    __syncthreads();
    float woff = 0.f, Tot = 0.f;
#pragma unroll
    for (int wdx = 0; wdx < 8; wdx++) {
        float v = wsum[wdx];
        Tot += v;
        if (wdx < (t >> 5)) woff += v;
    }
    float e = woff + (incl - s);
#pragma unroll
    for (int u = 0; u < 16; u++) Psh[PPAD + 16 * t + u + 1] = e + r[u];
    if (t == 0) Psh[PPAD] = 0.f;
    // Right pad: P[q>=4096] = total
    Psh[PPAD + LEN + 1 + t] = Tot;
    Psh[PPAD + LEN + 1 + t + 256] = Tot;
    __syncthreads();

    // ---- main convolution ----
    typedef unsigned long long u64;
    const u64 NEG1 = pk2(-1.0f, -1.0f);

    u64 acc[4][8];
    // skip: acc = x * D[c,h]
    u64 Dd[4];
#pragma unroll
    for (int c = 0; c < 4; c++) {
        float dv = D[c * HH + h];
        Dd[c] = pk2(dv, dv);
    }
#pragma unroll
    for (int j = 0; j < 8; j++) {
        int l0 = t + 512 * j;                 // lo l; hi = l0 + 256
        u64 x2 = pk2(Xsh[l0], Xsh[l0 + 256]);
#pragma unroll
        for (int c = 0; c < 4; c++) acc[c][j] = mul2(x2, Dd[c]);
    }

    const int O_[6] = {0, 32, 64, 128, 256, 512};
    const int R_[6] = {1, 1, 2, 4, 8, 16};
#pragma unroll
    for (int i = 0; i < 6; i++) {
        const int O = O_[i];
        const int R = R_[i];
        const int base = PPAD + t + 513 - O;  // min index 1, max 5120: in range
        u64 prev[8];
#pragma unroll
        for (int j = 0; j < 8; j++)
            prev[j] = pk2(Psh[base + 512 * j], Psh[base + 512 * j + 256]);
        const u64* wp = &Wsh[(i * 32) * 4];
        int off = base - R;
#pragma unroll 2
        for (int m = 0; m < 32; m++) {
            u64 w0 = wp[4 * m + 0];
            u64 w1 = wp[4 * m + 1];
            u64 w2 = wp[4 * m + 2];
            u64 w3 = wp[4 * m + 3];
#pragma unroll
            for (int j = 0; j < 8; j++) {
                u64 cur = pk2(Psh[off + 512 * j], Psh[off + 512 * j + 256]);
                u64 g = fma2(cur, NEG1, prev[j]);   // prev - cur
                prev[j] = cur;
                acc[0][j] = fma2(g, w0, acc[0][j]);
                acc[1][j] = fma2(g, w1, acc[1][j]);
                acc[2][j] = fma2(g, w2, acc[2][j]);
                acc[3][j] = fma2(g, w3, acc[3][j]);
            }
            off -= R;
        }
    }

    // ---- write out: out[((b*256+h)*4 + c)*4096 + l] ----
    float* outb = out + (size_t)(bb * HH + h) * 4 * LEN;
#pragma unroll
    for (int c = 0; c < 4; c++) {
        float* oc = outb + (size_t)c * LEN;
#pragma unroll
        for (int j = 0; j < 8; j++) {
            float lo, hi;
            upk2(acc[c][j], lo, hi);
            oc[t + 512 * j] = lo;
            oc[t + 512 * j + 256] = hi;
        }
    }
}

extern "C" void kernel_launch(void* const* d_in, const int* in_sizes, int n_in,
                              void* d_out, int out_size)
{
    const float* x    = (const float*)d_in[0];
    const float* kers = (const float*)d_in[1];
    const float* D    = (const float*)d_in[2];
    float* out = (float*)d_out;

    build_weights_kernel<<<HH, 128>>>(kers);
    conv_kernel<<<16 * HH, 256>>>(x, D, out);
}

// round 4
// speedup vs baseline: 1.5880x; 1.5847x over previous
#include <cuda_runtime.h>
#include <cstdint>

#define LEN 4096
#define HH 256
#define NTAPS 193   // 6*32 + 1 tail

typedef unsigned long long u64;

// Prebuilt difference weights: [h][T=0..192][c]
__device__ float g_W[HH * NTAPS * 4];

__device__ __forceinline__ u64 pk2(float a, float b) {
    u64 r;
    asm("mov.b64 %0, {%1, %2};" : "=l"(r) : "r"(__float_as_uint(a)), "r"(__float_as_uint(b)));
    return r;
}
__device__ __forceinline__ u64 fma2(u64 a, u64 b, u64 c) {
    u64 d;
    asm("fma.rn.f32x2 %0, %1, %2, %3;" : "=l"(d) : "l"(a), "l"(b), "l"(c));
    return d;
}
__device__ __forceinline__ u64 mul2(u64 a, u64 b) {
    u64 d;
    asm("mul.rn.f32x2 %0, %1, %2;" : "=l"(d) : "l"(a), "l"(b));
    return d;
}

// Build difference weights dw: conv = sum_T dw_T * Q[l + 513 - p_T],
// p_T = O_i + m*R_i for T=i*32+m, plus tail p=1024 with dw=-w[5][31].
// dw[i][m] = w[i][m]-w[i][m-1]; dw[i][0] = w[i][0]-w[i-1][31]; dw[0][0]=w[0][0].
__global__ void build_weights_kernel(const float* __restrict__ kers) {
    int h = blockIdx.x;
    int c = threadIdx.x >> 5;
    int lane = threadIdx.x & 31;
    const float normw[6] = {1024.f, 256.f, 128.f, 64.f, 32.f, 16.f};
    const float sc[6]    = {32.f, 16.f, 8.f, 4.f, 2.f, 1.f};

    float vals[6];
    float ss = 0.f;
#pragma unroll
    for (int i = 0; i < 6; i++) {
        float v = kers[((i * 4 + c) * HH + h) * 32 + lane];
        vals[i] = v * sc[i];
        ss += v * v * normw[i];
    }
#pragma unroll
    for (int o = 16; o; o >>= 1) ss += __shfl_xor_sync(0xffffffffu, ss, o);
    float inv = 1.0f / sqrtf(ss);

    float lastv = 0.f;
#pragma unroll
    for (int i = 0; i < 6; i++) {
        float nv = vals[i] * inv;
        float up = __shfl_up_sync(0xffffffffu, nv, 1);
        float dw = nv - ((lane == 0) ? lastv : up);
        g_W[(h * NTAPS + i * 32 + lane) * 4 + c] = dw;
        lastv = __shfl_sync(0xffffffffu, nv, 31);
    }
    if (lane == 0) g_W[(h * NTAPS + 192) * 4 + c] = -lastv;
}

// One CTA per (b,h). 256 threads, each owns 8 pairs of consecutive l:
// lo = 2t + 512*jj, hi = lo+1, jj in [0,8).
// Q[j] = prefix sum of x (Q[0]=0), zero-padded outside [0,4096].
// QA[k] = (Q[2k], Q[2k+1])      (used when tap position p is odd)
// QB[k+256 shift] = (Q[2k+1], Q[2k+2])  (used when p is even)
__global__ __launch_bounds__(256, 2) void conv_kernel(
    const float* __restrict__ x,
    const float* __restrict__ D,
    float* __restrict__ out)
{
    __shared__ float2 QAs[2560];           // indexed by k directly (k in [0,2303] used)
    __shared__ float2 QBs[2560];           // idx = k + 256, k in [-256, 2303]
    __shared__ u64 Wsh[NTAPS * 4 + 4];     // dup (w,w) pairs, [T][c]
    __shared__ float wsum[8];

    const int t  = threadIdx.x;
    const int h  = blockIdx.x & 255;
    const int bb = blockIdx.x >> 8;
    const float* xr = x + (size_t)(bb * HH + h) * LEN;

    float* xs = (float*)QBs;               // stage x here (4096 floats fit in 5120)

    // ---- phase A: stage x, load weights ----
#pragma unroll
    for (int it = 0; it < 16; it++) xs[t + 256 * it] = xr[t + 256 * it];
    for (int idx = t; idx < NTAPS * 4; idx += 256) {
        float w = g_W[h * (NTAPS * 4) + idx];
        Wsh[idx] = pk2(w, w);
    }
    u64 Dd[4];
#pragma unroll
    for (int c = 0; c < 4; c++) {
        float dv = D[c * HH + h];
        Dd[c] = pk2(dv, dv);
    }
    __syncthreads();

    // ---- phase B: pull x into regs (scan chunk + skip pairs), warp scan ----
    float r[16];
    {
        float4 v0 = *(const float4*)(xs + 16 * t + 0);
        float4 v1 = *(const float4*)(xs + 16 * t + 4);
        float4 v2 = *(const float4*)(xs + 16 * t + 8);
        float4 v3 = *(const float4*)(xs + 16 * t + 12);
        float run = 0.f;
        float vv[16] = {v0.x,v0.y,v0.z,v0.w, v1.x,v1.y,v1.z,v1.w,
                        v2.x,v2.y,v2.z,v2.w, v3.x,v3.y,v3.z,v3.w};
#pragma unroll
        for (int u = 0; u < 16; u++) { run += vv[u]; r[u] = run; }
    }
    u64 x2[8];
#pragma unroll
    for (int jj = 0; jj < 8; jj++) {
        float2 xv = *(const float2*)(xs + 2 * t + 512 * jj);
        x2[jj] = pk2(xv.x, xv.y);
    }
    float s = r[15];
    float incl = s;
#pragma unroll
    for (int o = 1; o < 32; o <<= 1) {
        float v = __shfl_up_sync(0xffffffffu, incl, o);
        if ((t & 31) >= o) incl += v;
    }
    if ((t & 31) == 31) wsum[t >> 5] = incl;
    __syncthreads();

    // ---- phase C: write pair arrays (overwrites staged x) ----
    float woff = 0.f, Tot = 0.f;
#pragma unroll
    for (int wdx = 0; wdx < 8; wdx++) {
        float v = wsum[wdx];
        Tot += v;
        if (wdx < (t >> 5)) woff += v;
    }
    float e = woff + (incl - s);           // e = Q[16t]
    float qv[17];
    qv[0] = e;
#pragma unroll
    for (int u = 0; u < 16; u++) qv[u + 1] = e + r[u];
#pragma unroll
    for (int u = 0; u < 8; u++) {
        QAs[8 * t + u]       = make_float2(qv[2 * u],     qv[2 * u + 1]);
        QBs[256 + 8 * t + u] = make_float2(qv[2 * u + 1], qv[2 * u + 2]);
    }
    QBs[t] = make_float2(0.f, 0.f);                 // left pad k in [-256,-1]
    QAs[2048 + t] = make_float2(Tot, Tot);          // right pad k in [2048,2303]
    QBs[2304 + t] = make_float2(Tot, Tot);
    __syncthreads();

    // ---- conv: acc init with skip, then 193 taps ----
    u64 acc[4][8];
#pragma unroll
    for (int jj = 0; jj < 8; jj++)
#pragma unroll
        for (int c = 0; c < 4; c++) acc[c][jj] = mul2(x2[jj], Dd[c]);

    // scales 0+1 (R=1, p=T for T=0..63): even p -> QB, odd p -> QA
    {
        const float2* pB = QBs + 512 + t;   // p=2m: idx = t+256jj+512-m
        const float2* pA = QAs + 256 + t;   // p=2m+1: idx = t+256jj+256-m
#pragma unroll 4
        for (int m = 0; m < 32; m++) {
            ulonglong2 we01 = *(const ulonglong2*)(Wsh + 8 * m + 0);
            ulonglong2 we23 = *(const ulonglong2*)(Wsh + 8 * m + 2);
            ulonglong2 wo01 = *(const ulonglong2*)(Wsh + 8 * m + 4);
            ulonglong2 wo23 = *(const ulonglong2*)(Wsh + 8 * m + 6);
#pragma unroll
            for (int jj = 0; jj < 8; jj++) {
                u64 qb = *(const u64*)(pB + 256 * jj - m);
                acc[0][jj] = fma2(qb, we01.x, acc[0][jj]);
                acc[1][jj] = fma2(qb, we01.y, acc[1][jj]);
                acc[2][jj] = fma2(qb, we23.x, acc[2][jj]);
                acc[3][jj] = fma2(qb, we23.y, acc[3][jj]);
                u64 qa = *(const u64*)(pA + 256 * jj - m);
                acc[0][jj] = fma2(qa, wo01.x, acc[0][jj]);
                acc[1][jj] = fma2(qa, wo01.y, acc[1][jj]);
                acc[2][jj] = fma2(qa, wo23.x, acc[2][jj]);
                acc[3][jj] = fma2(qa, wo23.y, acc[3][jj]);
            }
        }
    }

    // scales 2..5: all even p -> QB only. idx = t+256jj + K0 - S*m
    {
        const int K0_[4] = {480, 448, 384, 256};
        const int S_[4]  = {1, 2, 4, 8};
#pragma unroll
        for (int sc = 0; sc < 4; sc++) {
            const float2* pB = QBs + K0_[sc] + t;
            const int S = S_[sc];
            const u64* wp = Wsh + (64 + sc * 32) * 4;
#pragma unroll 4
            for (int m = 0; m < 32; m++) {
                ulonglong2 w01 = *(const ulonglong2*)(wp + 4 * m + 0);
                ulonglong2 w23 = *(const ulonglong2*)(wp + 4 * m + 2);
#pragma unroll
                for (int jj = 0; jj < 8; jj++) {
                    u64 q = *(const u64*)(pB + 256 * jj - S * m);
                    acc[0][jj] = fma2(q, w01.x, acc[0][jj]);
                    acc[1][jj] = fma2(q, w01.y, acc[1][jj]);
                    acc[2][jj] = fma2(q, w23.x, acc[2][jj]);
                    acc[3][jj] = fma2(q, w23.y, acc[3][jj]);
                }
            }
        }
    }

    // tail tap p=1024: idx = t + 256jj
    {
        const float2* pB = QBs + t;
        ulonglong2 w01 = *(const ulonglong2*)(Wsh + 192 * 4 + 0);
        ulonglong2 w23 = *(const ulonglong2*)(Wsh + 192 * 4 + 2);
#pragma unroll
        for (int jj = 0; jj < 8; jj++) {
            u64 q = *(const u64*)(pB + 256 * jj);
            acc[0][jj] = fma2(q, w01.x, acc[0][jj]);
            acc[1][jj] = fma2(q, w01.y, acc[1][jj]);
            acc[2][jj] = fma2(q, w23.x, acc[2][jj]);
            acc[3][jj] = fma2(q, w23.y, acc[3][jj]);
        }
    }

    // ---- output: out[((bb*256+h)*4 + c)*4096 + l], pairs are consecutive l ----
    float* outb = out + (size_t)(bb * HH + h) * 4 * LEN;
#pragma unroll
    for (int c = 0; c < 4; c++) {
        float* oc = outb + (size_t)c * LEN;
#pragma unroll
        for (int jj = 0; jj < 8; jj++) {
            *(u64*)(oc + 2 * t + 512 * jj) = acc[c][jj];
        }
    }
}

extern "C" void kernel_launch(void* const* d_in, const int* in_sizes, int n_in,
                              void* d_out, int out_size)
{
    const float* x    = (const float*)d_in[0];
    const float* kers = (const float*)d_in[1];
    const float* D    = (const float*)d_in[2];
    float* out = (float*)d_out;

    build_weights_kernel<<<HH, 128>>>(kers);
    conv_kernel<<<16 * HH, 256>>>(x, D, out);
}

// round 5
// speedup vs baseline: 1.7662x; 1.1122x over previous
#include <cuda_runtime.h>
#include <cstdint>

#define LEN 4096
#define HH 256
#define NT 194          // 192 diff-taps + tail(p=1024) + skip-odd(p=513)
#define QROW 6144       // [0,1024): zeros | [1024,1024+4097): Q | rest: Tot

typedef unsigned long long u64;

__device__ float g_W[HH * NT * 4];          // [h][T][c] difference weights
__device__ float g_Q[4096 * QROW];          // padded prefix sums per (b,h) row

__device__ __forceinline__ u64 pk2(float a, float b) {
    u64 r;
    asm("mov.b64 %0, {%1, %2};" : "=l"(r) : "r"(__float_as_uint(a)), "r"(__float_as_uint(b)));
    return r;
}
__device__ __forceinline__ u64 fma2(u64 a, u64 b, u64 c) {
    u64 d;
    asm("fma.rn.f32x2 %0, %1, %2, %3;" : "=l"(d) : "l"(a), "l"(b), "l"(c));
    return d;
}

// ---------------- weight build: difference weights + folded skip ----------------
// conv[l] = sum_T dw_T * Q[l + 513 - p_T]
// p_T = O_i + m*R_i (T = i*32+m), p_192 = 1024, p_193 = 513 (odd, skip)
__global__ void build_weights_kernel(const float* __restrict__ kers,
                                     const float* __restrict__ D) {
    int h = blockIdx.x;
    int c = threadIdx.x >> 5;
    int lane = threadIdx.x & 31;
    const float normw[6] = {1024.f, 256.f, 128.f, 64.f, 32.f, 16.f};
    const float sc[6]    = {32.f, 16.f, 8.f, 4.f, 2.f, 1.f};

    float vals[6];
    float ss = 0.f;
#pragma unroll
    for (int i = 0; i < 6; i++) {
        float v = kers[((i * 4 + c) * HH + h) * 32 + lane];
        vals[i] = v * sc[i];
        ss += v * v * normw[i];
    }
#pragma unroll
    for (int o = 16; o; o >>= 1) ss += __shfl_xor_sync(0xffffffffu, ss, o);
    float inv = 1.0f / sqrtf(ss);
    float dv = D[c * HH + h];

    float lastv = 0.f;
#pragma unroll
    for (int i = 0; i < 6; i++) {
        float nv = vals[i] * inv;
        float up = __shfl_up_sync(0xffffffffu, nv, 1);
        float dw = nv - ((lane == 0) ? lastv : up);
        if (i == 5 && lane == 0) dw += dv;          // p=512 tap absorbs +D
        g_W[(h * NT + i * 32 + lane) * 4 + c] = dw;
        lastv = __shfl_sync(0xffffffffu, nv, 31);
    }
    if (lane == 0) {
        g_W[(h * NT + 192) * 4 + c] = -lastv;       // tail p=1024
        g_W[(h * NT + 193) * 4 + c] = -dv;          // skip odd tap p=513
    }
}

// ---------------- scan: padded prefix sums to gmem ----------------
__global__ __launch_bounds__(256) void scan_kernel(const float* __restrict__ x) {
    __shared__ float Psh[4097];
    __shared__ float wsum[8];
    int t = threadIdx.x;
    int row = blockIdx.x;
    const float* xr = x + (size_t)row * LEN;

    float vv[16];
#pragma unroll
    for (int u = 0; u < 4; u++) {
        float4 v = *(const float4*)(xr + 16 * t + 4 * u);
        vv[4*u] = v.x; vv[4*u+1] = v.y; vv[4*u+2] = v.z; vv[4*u+3] = v.w;
    }
    float r[16];
    float run = 0.f;
#pragma unroll
    for (int u = 0; u < 16; u++) { run += vv[u]; r[u] = run; }
    float incl = run;
#pragma unroll
    for (int o = 1; o < 32; o <<= 1) {
        float v = __shfl_up_sync(0xffffffffu, incl, o);
        if ((t & 31) >= o) incl += v;
    }
    if ((t & 31) == 31) wsum[t >> 5] = incl;
    __syncthreads();
    float woff = 0.f, Tot = 0.f;
#pragma unroll
    for (int w = 0; w < 8; w++) {
        float v = wsum[w];
        Tot += v;
        if (w < (t >> 5)) woff += v;
    }
    float e = woff + (incl - run);
    if (t == 0) Psh[0] = 0.f;
#pragma unroll
    for (int u = 0; u < 16; u++) Psh[16 * t + u + 1] = e + r[u];
    __syncthreads();

    float* qr = g_Q + (size_t)row * QROW;
    float4 z4 = make_float4(0.f, 0.f, 0.f, 0.f);
    *(float4*)(qr + 4 * t) = z4;                          // zeros [0,1024)
#pragma unroll
    for (int u = 0; u < 16; u++) qr[1024 + t + 256 * u] = Psh[t + 256 * u];
    if (t == 0) qr[1024 + 4096] = Psh[4096];
#pragma unroll
    for (int u = 0; u < 4; u++) {                         // Tot pad [5121, 6144)
        int i = 5121 + t + 256 * u;
        if (i < QROW) qr[i] = Tot;
    }
}

// ---------------- conv: one CTA per (row, half), 8 l per thread ----------------
__device__ __forceinline__ void dotap(u64 acc[4][4], const float2* p, int koff,
                                      const float4* __restrict__ Wsh, int T) {
    float4 w4 = Wsh[T];
    u64 w0 = pk2(w4.x, w4.x);
    u64 w1 = pk2(w4.y, w4.y);
    u64 w2 = pk2(w4.z, w4.z);
    u64 w3 = pk2(w4.w, w4.w);
#pragma unroll
    for (int jj = 0; jj < 4; jj++) {
        u64 q = *(const u64*)(p + koff + 256 * jj);
        acc[0][jj] = fma2(q, w0, acc[0][jj]);
        acc[1][jj] = fma2(q, w1, acc[1][jj]);
        acc[2][jj] = fma2(q, w2, acc[2][jj]);
        acc[3][jj] = fma2(q, w3, acc[3][jj]);
    }
}

__global__ __launch_bounds__(256, 3) void conv_kernel(float* __restrict__ out) {
    __shared__ float2 QA[1536];   // QA[k] = (Qw[2k],   Qw[2k+1]),  Qw[i] = Q[base-512+i]
    __shared__ float2 QB[1536];   // QB[k] = (Qw[2k+1], Qw[2k+2])
    __shared__ float4 Wsh[NT];

    const int t = threadIdx.x;
    const int row = blockIdx.x >> 1;         // bb*256 + h
    const int half = blockIdx.x & 1;
    const int h = row & 255;
    const int base = half * 2048;

    // window: Qw[0..3072], gmem idx = row*QROW + 1024 + (base-512) + i
    const float* qw = g_Q + (size_t)row * QROW + 512 + base;
#pragma unroll
    for (int u = 0; u < 6; u++) {
        int k = t + 256 * u;                 // k in [0,1536)
        float2 a = *(const float2*)(qw + 2 * k);
        float2 b = *(const float2*)(qw + 2 * k + 2);
        QA[k] = a;
        QB[k] = make_float2(a.y, b.x);
    }
    if (t < NT) Wsh[t] = *(const float4*)(g_W + (h * NT + t) * 4);
    __syncthreads();

    u64 acc[4][4] = {};
    const float2* pA = QA + t;
    const float2* pB = QB + t;

    // scales 0,1 (R=1): per mm process even tap (QB) + odd tap (QA), same koff
#pragma unroll 4
    for (int mm = 0; mm < 16; mm++) {
        dotap(acc, pB, 512 - mm, Wsh, 2 * mm);
        dotap(acc, pA, 512 - mm, Wsh, 2 * mm + 1);
    }
#pragma unroll 4
    for (int mm = 0; mm < 16; mm++) {
        dotap(acc, pB, 496 - mm, Wsh, 32 + 2 * mm);
        dotap(acc, pA, 496 - mm, Wsh, 33 + 2 * mm);
    }
    // scales 2..5: even p -> QB
#pragma unroll 8
    for (int m = 0; m < 32; m++) dotap(acc, pB, 480 - m,     Wsh, 64 + m);
#pragma unroll 8
    for (int m = 0; m < 32; m++) dotap(acc, pB, 448 - 2 * m, Wsh, 96 + m);
#pragma unroll 8
    for (int m = 0; m < 32; m++) dotap(acc, pB, 384 - 4 * m, Wsh, 128 + m);
#pragma unroll 8
    for (int m = 0; m < 32; m++) dotap(acc, pB, 256 - 8 * m, Wsh, 160 + m);
    dotap(acc, pB, 0,   Wsh, 192);   // tail p=1024
    dotap(acc, pA, 256, Wsh, 193);   // skip p=513

    // out[((row)*4 + c)*4096 + base + 2t + 512jj]
    float* outb = out + (size_t)row * 4 * LEN + base;
#pragma unroll
    for (int c = 0; c < 4; c++) {
        float* oc = outb + (size_t)c * LEN;
#pragma unroll
        for (int jj = 0; jj < 4; jj++)
            *(u64*)(oc + 2 * t + 512 * jj) = acc[c][jj];
    }
}

extern "C" void kernel_launch(void* const* d_in, const int* in_sizes, int n_in,
                              void* d_out, int out_size)
{
    const float* x    = (const float*)d_in[0];
    const float* kers = (const float*)d_in[1];
    const float* D    = (const float*)d_in[2];
    float* out = (float*)d_out;

    build_weights_kernel<<<HH, 128>>>(kers, D);
    scan_kernel<<<4096, 256>>>(x);
    conv_kernel<<<8192, 256>>>(out);
}